// round 15
// baseline (speedup 1.0000x reference)
#include <cuda_runtime.h>
#include <cuda_bf16.h>
#include <mma.h>
#include <cstdint>

using namespace nvcuda;

#define N_NODES   100000
#define N_EDGES   1600000
#define D_FEAT    128
#define HIDDEN    128
#define N_CLASSES 10
#define NUM_GRAPHS 64
#define N_PAD     100096   // 782 * 128, full-tile padding for direct wmma stores
#define NBLK      391      // ceil(N_NODES / 256)

typedef __nv_bfloat16 bf16;
typedef __nv_bfloat162 bf162;

#define LDT 72             // padded bf16 row length for 64-col tiles

// ---------------- scratch (no allocs allowed) ----------------
__device__ float g_agg[(size_t)N_PAD * 128];
__device__ float g_h1 [(size_t)N_PAD * 128];
__device__ float g_h2 [(size_t)N_PAD * 128];
// weights pre-split, chunk-tiled SMEM-ready: [3 layers][4 chunks][128 n][LDT]
__device__ bf16  g_whi[3 * 4 * 128 * LDT];
__device__ bf16  g_wlo[3 * 4 * 128 * LDT];
__device__ float g_pooled[NUM_GRAPHS * HIDDEN];
__device__ int   g_deg [N_NODES];
__device__ int   g_off [N_NODES + 1];
__device__ int   g_cur [N_NODES];
__device__ int   g_srcs[N_EDGES];
__device__ int   g_blksum[NBLK];
__device__ int   g_blkoff[NBLK];

// ---------------- helpers ----------------
__device__ __forceinline__ uint32_t smem_u32(const void* p) {
    uint32_t a;
    asm("{ .reg .u64 t; cvta.to.shared.u64 t, %1; cvt.u32.u64 %0, t; }" : "=r"(a) : "l"(p));
    return a;
}
__device__ __forceinline__ void cp16(uint32_t dst, const void* src) {
    asm volatile("cp.async.cg.shared.global [%0], [%1], 16;" :: "r"(dst), "l"(src));
}
#define CP_COMMIT() asm volatile("cp.async.commit_group;" ::: "memory")
#define CP_WAIT1()  asm volatile("cp.async.wait_group 1;" ::: "memory")
#define CP_WAIT0()  asm volatile("cp.async.wait_group 0;" ::: "memory")

__device__ __forceinline__ void split4(float4 v, uint2& hi, uint2& lo) {
    bf162 h0, h1, l0, l1;
    h0.x = __float2bfloat16(v.x); h0.y = __float2bfloat16(v.y);
    h1.x = __float2bfloat16(v.z); h1.y = __float2bfloat16(v.w);
    l0.x = __float2bfloat16(v.x - __bfloat162float(h0.x));
    l0.y = __float2bfloat16(v.y - __bfloat162float(h0.y));
    l1.x = __float2bfloat16(v.z - __bfloat162float(h1.x));
    l1.y = __float2bfloat16(v.w - __bfloat162float(h1.y));
    hi.x = *reinterpret_cast<uint32_t*>(&h0); hi.y = *reinterpret_cast<uint32_t*>(&h1);
    lo.x = *reinterpret_cast<uint32_t*>(&l0); lo.y = *reinterpret_cast<uint32_t*>(&l1);
}

// ---------------- weight conversion (one-time) ----------------
__global__ void __launch_bounds__(256) cvt_w_kernel(
    const float* __restrict__ W1l, const float* __restrict__ W1r,
    const float* __restrict__ W2l, const float* __restrict__ W2r,
    const float* __restrict__ W3l, const float* __restrict__ W3r,
    bf16* __restrict__ whi, bf16* __restrict__ wlo)
{
    int id = blockIdx.x * blockDim.x + threadIdx.x;   // 3*128*64 quads
    if (id >= 3 * 128 * 64) return;
    int l = id / (128 * 64);
    int n = (id / 64) % 128;
    int k = (id & 63) * 4;            // 0..252
    const float* Wl = (l == 0) ? W1l : (l == 1) ? W2l : W3l;
    const float* Wr = (l == 0) ? W1r : (l == 1) ? W2r : W3r;
    float4 v;
    if (k < 128) v = __ldg(reinterpret_cast<const float4*>(Wl + n * 128 + k));
    else         v = __ldg(reinterpret_cast<const float4*>(Wr + n * 128 + k - 128));
    uint2 hi, lo;
    split4(v, hi, lo);
    int c  = k >> 6;
    int kk = k & 63;
    size_t dst = ((size_t)(l * 4 + c) * 128 + n) * LDT + kk;
    *reinterpret_cast<uint2*>(whi + dst) = hi;
    *reinterpret_cast<uint2*>(wlo + dst) = lo;
}

// ---------------- CSR build ----------------
__global__ void __launch_bounds__(256) hist_kernel(
    const int* __restrict__ ei, int* __restrict__ deg)
{
    int e = blockIdx.x * blockDim.x + threadIdx.x;
    if (e >= N_EDGES) return;
    atomicAdd(deg + __ldg(ei + N_EDGES + e), 1);
}
__global__ void __launch_bounds__(256) partial_kernel(
    const int* __restrict__ deg, int* __restrict__ blksum)
{
    __shared__ int wsum[8];
    int i = blockIdx.x * 256 + threadIdx.x;
    int v = (i < N_NODES) ? deg[i] : 0;
#pragma unroll
    for (int d = 16; d > 0; d >>= 1) v += __shfl_down_sync(0xffffffffu, v, d);
    if ((threadIdx.x & 31) == 0) wsum[threadIdx.x >> 5] = v;
    __syncthreads();
    if (threadIdx.x < 8) {
        int s = wsum[threadIdx.x];
#pragma unroll
        for (int d = 4; d > 0; d >>= 1) s += __shfl_down_sync(0xffu, s, d);
        if (threadIdx.x == 0) blksum[blockIdx.x] = s;
    }
}
__global__ void __launch_bounds__(512) scan_blocks_kernel(
    const int* __restrict__ blksum, int* __restrict__ blkoff)
{
    __shared__ int sh[512];
    int t = threadIdx.x;
    sh[t] = (t < NBLK) ? blksum[t] : 0;
    __syncthreads();
#pragma unroll
    for (int d = 1; d < 512; d <<= 1) {
        int v = (t >= d) ? sh[t - d] : 0;
        __syncthreads();
        sh[t] += v;
        __syncthreads();
    }
    if (t < NBLK) blkoff[t] = sh[t] - blksum[t];   // exclusive
}
__global__ void __launch_bounds__(256) fill_off_kernel(
    const int* __restrict__ deg, const int* __restrict__ blkoff,
    int* __restrict__ off, int* __restrict__ cur)
{
    __shared__ int sh[256];
    int t = threadIdx.x;
    int i = blockIdx.x * 256 + t;
    int v = (i < N_NODES) ? deg[i] : 0;
    sh[t] = v;
    __syncthreads();
#pragma unroll
    for (int d = 1; d < 256; d <<= 1) {
        int u = (t >= d) ? sh[t - d] : 0;
        __syncthreads();
        sh[t] += u;
        __syncthreads();
    }
    if (i < N_NODES) {
        int excl = blkoff[blockIdx.x] + sh[t] - v;
        off[i] = excl;
        cur[i] = excl;
    }
    if (blockIdx.x == 0 && t == 0) off[N_NODES] = N_EDGES;
}
__global__ void __launch_bounds__(256) fill_kernel(
    const int* __restrict__ ei, int* __restrict__ cur, int* __restrict__ srcs)
{
    int e = blockIdx.x * blockDim.x + threadIdx.x;
    if (e >= N_EDGES) return;
    int src = __ldg(ei + e);
    int dst = __ldg(ei + N_EDGES + e);
    int pos = atomicAdd(cur + dst, 1);
    srcs[pos] = src;
}

// ---------------- gather aggregation (fp32) ----------------
__global__ void __launch_bounds__(256) aggregate_kernel(
    const float* __restrict__ h,
    const int*   __restrict__ off,
    const int*   __restrict__ srcs,
    float*       __restrict__ agg)
{
    int node = (blockIdx.x * blockDim.x + threadIdx.x) >> 5;
    int lane = threadIdx.x & 31;
    if (node >= N_NODES) return;
    int b = __ldg(off + node);
    int e = __ldg(off + node + 1);
    float4 acc = make_float4(0.f, 0.f, 0.f, 0.f);
    int i = b;
    for (; i + 3 < e; i += 4) {
        int s0 = __ldg(srcs + i + 0);
        int s1 = __ldg(srcs + i + 1);
        int s2 = __ldg(srcs + i + 2);
        int s3 = __ldg(srcs + i + 3);
        float4 v0 = __ldg(reinterpret_cast<const float4*>(h + (size_t)s0 * 128) + lane);
        float4 v1 = __ldg(reinterpret_cast<const float4*>(h + (size_t)s1 * 128) + lane);
        float4 v2 = __ldg(reinterpret_cast<const float4*>(h + (size_t)s2 * 128) + lane);
        float4 v3 = __ldg(reinterpret_cast<const float4*>(h + (size_t)s3 * 128) + lane);
        acc.x += (v0.x + v1.x) + (v2.x + v3.x);
        acc.y += (v0.y + v1.y) + (v2.y + v3.y);
        acc.z += (v0.z + v1.z) + (v2.z + v3.z);
        acc.w += (v0.w + v1.w) + (v2.w + v3.w);
    }
    for (; i < e; ++i) {
        int s = __ldg(srcs + i);
        float4 v = __ldg(reinterpret_cast<const float4*>(h + (size_t)s * 128) + lane);
        acc.x += v.x; acc.y += v.y; acc.z += v.z; acc.w += v.w;
    }
    *(reinterpret_cast<float4*>(agg + (size_t)node * 128) + lane) = acc;
}

// ================ WMMA bf16x2 SAGE GEMM (R11) + fused pooling ================
#define A_HI_OFF 0
#define A_LO_OFF 18432
#define B_BASE   36864
#define B_STAGE  36864              // hi 18432 + lo 18432
#define SM_TOTAL (B_BASE + 2 * B_STAGE)   // 110592 -> 2 CTAs/SM

__device__ __forceinline__ void load_B(
    int c, uint32_t stg, const bf16* whi, const bf16* wlo, int tid)
{
    const int r = tid >> 1;          // 0..127 (n)
    const int half = (tid & 1) * 32; // k offset within chunk
    const bf16* srcH = whi + ((size_t)c * 128 + r) * LDT + half;
    const bf16* srcL = wlo + ((size_t)c * 128 + r) * LDT + half;
    uint32_t dH = stg + r * (LDT * 2) + half * 2;
    uint32_t dL = stg + 18432 + r * (LDT * 2) + half * 2;
#pragma unroll
    for (int i = 0; i < 4; ++i) {
        cp16(dH + i * 16, srcH + i * 8);
        cp16(dL + i * 16, srcL + i * 8);
    }
}

__global__ void __launch_bounds__(256)
sage_wmma_kernel(
    const float* __restrict__ agg,
    const float* __restrict__ h,
    const bf16*  __restrict__ whi,   // layer base, chunk-tiled
    const bf16*  __restrict__ wlo,
    const float* __restrict__ bias,
    float*       __restrict__ out,   // padded to N_PAD rows (unused if pool_mode)
    const int*   __restrict__ batch,
    float*       __restrict__ pooled,
    int do_relu, int pool_mode)
{
    extern __shared__ char smem[];
    const uint32_t sbase = smem_u32(smem);
    bf16* sAhi = reinterpret_cast<bf16*>(smem + A_HI_OFF);
    bf16* sAlo = reinterpret_cast<bf16*>(smem + A_LO_OFF);

    const int tid = threadIdx.x;
    const int wid = tid >> 5;
    const int block_row = blockIdx.x * 128;

    const int row  = tid >> 1;
    const int c0   = (tid & 1) * 32;
    const bool aok = (block_row + row) < N_NODES;

    const int wm = (wid & 1) * 64;
    const int wn = (wid >> 1) * 32;

    wmma::fragment<wmma::accumulator, 16, 16, 16, float> acc[4][2];
#pragma unroll
    for (int i = 0; i < 4; ++i)
#pragma unroll
        for (int j = 0; j < 2; ++j) wmma::fill_fragment(acc[i][j], 0.f);

    load_B(0, sbase + B_BASE,           whi, wlo, tid);
    CP_COMMIT();
    load_B(1, sbase + B_BASE + B_STAGE, whi, wlo, tid);
    CP_COMMIT();

    float4 av[8];
    {
        const float* ap = agg + (size_t)(block_row + row) * 128 + c0;
#pragma unroll
        for (int j = 0; j < 8; ++j)
            av[j] = aok ? __ldg(reinterpret_cast<const float4*>(ap) + j)
                        : make_float4(0.f, 0.f, 0.f, 0.f);
    }

#pragma unroll 1
    for (int c = 0; c < 4; ++c) {
#pragma unroll
        for (int j = 0; j < 8; ++j) {
            int eoff = row * LDT + c0 + j * 4;
            uint2 hi, lo;
            split4(av[j], hi, lo);
            *reinterpret_cast<uint2*>(sAhi + eoff) = hi;
            *reinterpret_cast<uint2*>(sAlo + eoff) = lo;
        }
        if (c < 3) CP_WAIT1(); else CP_WAIT0();
        __syncthreads();

        if (c < 3) {
            const int nc = c + 1;
            const float* Asrc = (nc < 2) ? agg : h;
            const int k0 = (nc & 1) * 64;
            const float* ap = Asrc + (size_t)(block_row + row) * 128 + k0 + c0;
#pragma unroll
            for (int j = 0; j < 8; ++j)
                av[j] = aok ? __ldg(reinterpret_cast<const float4*>(ap) + j)
                            : make_float4(0.f, 0.f, 0.f, 0.f);
        }

        const char* st = smem + B_BASE + (c & 1) * B_STAGE;
        const bf16* sBhi = reinterpret_cast<const bf16*>(st);
        const bf16* sBlo = reinterpret_cast<const bf16*>(st + 18432);

#pragma unroll
        for (int ks = 0; ks < 4; ++ks) {
            wmma::fragment<wmma::matrix_a, 16, 16, 16, bf16, wmma::row_major> fah[4], fal[4];
#pragma unroll
            for (int i = 0; i < 4; ++i) {
                wmma::load_matrix_sync(fah[i], sAhi + (wm + i * 16) * LDT + ks * 16, LDT);
                wmma::load_matrix_sync(fal[i], sAlo + (wm + i * 16) * LDT + ks * 16, LDT);
            }
#pragma unroll
            for (int j = 0; j < 2; ++j) {
                wmma::fragment<wmma::matrix_b, 16, 16, 16, bf16, wmma::col_major> fbh, fbl;
                wmma::load_matrix_sync(fbh, sBhi + (wn + j * 16) * LDT + ks * 16, LDT);
                wmma::load_matrix_sync(fbl, sBlo + (wn + j * 16) * LDT + ks * 16, LDT);
#pragma unroll
                for (int i = 0; i < 4; ++i) {
                    wmma::mma_sync(acc[i][j], fah[i], fbh, acc[i][j]);
                    wmma::mma_sync(acc[i][j], fah[i], fbl, acc[i][j]);
                    wmma::mma_sync(acc[i][j], fal[i], fbh, acc[i][j]);
                }
            }
        }
        __syncthreads();
        if (c + 2 < 4) {
            load_B(c + 2, sbase + B_BASE + (c & 1) * B_STAGE, whi, wlo, tid);
            CP_COMMIT();
        }
    }

    if (!pool_mode) {
        // ---- standard epilogue: replicated bias, in-fragment add/relu, direct store ----
        float* sBias = reinterpret_cast<float*>(smem);
        for (int idx = tid; idx < 16 * 128; idx += 256)
            sBias[idx] = __ldg(bias + (idx & 127));
        __syncthreads();

#pragma unroll
        for (int j = 0; j < 2; ++j) {
            wmma::fragment<wmma::accumulator, 16, 16, 16, float> bf;
            wmma::load_matrix_sync(bf, sBias + wn + j * 16, 128, wmma::mem_row_major);
#pragma unroll
            for (int i = 0; i < 4; ++i) {
#pragma unroll
                for (int e = 0; e < acc[i][j].num_elements; ++e) {
                    float v = acc[i][j].x[e] + bf.x[e];
                    acc[i][j].x[e] = do_relu ? fmaxf(v, 0.f) : v;
                }
                float* op = out + (size_t)(block_row + wm + i * 16) * 128 + wn + j * 16;
                wmma::store_matrix_sync(op, acc[i][j], 128, wmma::mem_row_major);
            }
        }
    } else {
        // ---- fused pooling epilogue (layer 3, no relu): frags -> SMEM f32,
        //      bias add, red.add into pooled[batch[row]]; h output not written ----
        float* sEpi = reinterpret_cast<float*>(smem);   // 128 x 132
#pragma unroll
        for (int i = 0; i < 4; ++i)
#pragma unroll
            for (int j = 0; j < 2; ++j)
                wmma::store_matrix_sync(sEpi + (wm + i * 16) * 132 + wn + j * 16,
                                        acc[i][j], 132, wmma::mem_row_major);
        __syncthreads();

        const int grow = block_row + row;
        if (grow < N_NODES) {
            const int g = __ldg(batch + grow);
            float* pbase = pooled + (size_t)g * HIDDEN + c0 * 2;  // c0*2: 0 or 64
#pragma unroll
            for (int cb = 0; cb < 64; cb += 4) {
                float4 v = *reinterpret_cast<const float4*>(sEpi + row * 132 + c0 * 2 + cb);
                float4 b = __ldg(reinterpret_cast<const float4*>(bias + c0 * 2 + cb));
                v.x += b.x; v.y += b.y; v.z += b.z; v.w += b.w;
                asm volatile("red.global.add.v4.f32 [%0], {%1,%2,%3,%4};"
                             :: "l"(pbase + cb), "f"(v.x), "f"(v.y), "f"(v.z), "f"(v.w)
                             : "memory");
            }
        }
    }
}

// ---------------- output head ----------------
__global__ void out_kernel(
    const float* __restrict__ pooled,
    const float* __restrict__ Wout,
    const float* __restrict__ bout,
    float*       __restrict__ out)
{
    int idx = blockIdx.x * blockDim.x + threadIdx.x;
    if (idx >= NUM_GRAPHS * N_CLASSES) return;
    int g = idx / N_CLASSES;
    int c = idx % N_CLASSES;
    float s = __ldg(bout + c);
    const float* p = pooled + (size_t)g * HIDDEN;
    const float* w = Wout + (size_t)c * HIDDEN;
#pragma unroll 8
    for (int k = 0; k < HIDDEN; ++k) s = fmaf(p[k], w[k], s);
    out[idx] = s;
}

// ---------------- launch ----------------
extern "C" void kernel_launch(void* const* d_in, const int* in_sizes, int n_in,
                              void* d_out, int out_size)
{
    const float* x     = (const float*)d_in[0];
    const int*   ei    = (const int*)  d_in[1];
    const int*   batch = (const int*)  d_in[2];
    const float* W1l = (const float*)d_in[3];
    const float* b1  = (const float*)d_in[4];
    const float* W1r = (const float*)d_in[5];
    const float* W2l = (const float*)d_in[6];
    const float* b2  = (const float*)d_in[7];
    const float* W2r = (const float*)d_in[8];
    const float* W3l = (const float*)d_in[9];
    const float* b3  = (const float*)d_in[10];
    const float* W3r = (const float*)d_in[11];
    const float* Wout = (const float*)d_in[12];
    const float* bout = (const float*)d_in[13];
    float* out = (float*)d_out;

    float *agg, *h1, *h2, *pooled;
    bf16 *whi, *wlo;
    int *deg, *off, *cur, *srcs, *blksum, *blkoff;
    cudaGetSymbolAddress((void**)&agg,    g_agg);
    cudaGetSymbolAddress((void**)&h1,     g_h1);
    cudaGetSymbolAddress((void**)&h2,     g_h2);
    cudaGetSymbolAddress((void**)&whi,    g_whi);
    cudaGetSymbolAddress((void**)&wlo,    g_wlo);
    cudaGetSymbolAddress((void**)&pooled, g_pooled);
    cudaGetSymbolAddress((void**)&deg,    g_deg);
    cudaGetSymbolAddress((void**)&off,    g_off);
    cudaGetSymbolAddress((void**)&cur,    g_cur);
    cudaGetSymbolAddress((void**)&srcs,   g_srcs);
    cudaGetSymbolAddress((void**)&blksum, g_blksum);
    cudaGetSymbolAddress((void**)&blkoff, g_blkoff);

    cudaFuncSetAttribute(sage_wmma_kernel,
                         cudaFuncAttributeMaxDynamicSharedMemorySize, SM_TOTAL);

    const int edge_blocks = (N_EDGES + 255) / 256;
    const int node_blocks = NBLK;
    const int gemm_blocks = N_PAD / 128;   // 782
    const int warp_blocks = (N_NODES * 32 + 255) / 256;
    const int WSTRIDE = 4 * 128 * LDT;     // per-layer weight stride

    // one-time weight conversion
    cvt_w_kernel<<<(3 * 128 * 64 + 255) / 256, 256>>>(W1l, W1r, W2l, W2r, W3l, W3r, whi, wlo);

    // CSR build (multi-block scan)
    cudaMemsetAsync(deg, 0, N_NODES * sizeof(int));
    hist_kernel<<<edge_blocks, 256>>>(ei, deg);
    partial_kernel<<<node_blocks, 256>>>(deg, blksum);
    scan_blocks_kernel<<<1, 512>>>(blksum, blkoff);
    fill_off_kernel<<<node_blocks, 256>>>(deg, blkoff, off, cur);
    fill_kernel<<<edge_blocks, 256>>>(ei, cur, srcs);

    // layer 1: x -> h1
    aggregate_kernel<<<warp_blocks, 256>>>(x, off, srcs, agg);
    sage_wmma_kernel<<<gemm_blocks, 256, SM_TOTAL>>>(agg, x, whi, wlo, b1,
                                                     h1, batch, pooled, 1, 0);

    // layer 2: h1 -> h2
    aggregate_kernel<<<warp_blocks, 256>>>(h1, off, srcs, agg);
    sage_wmma_kernel<<<gemm_blocks, 256, SM_TOTAL>>>(agg, h1, whi + WSTRIDE, wlo + WSTRIDE, b2,
                                                     h2, batch, pooled, 1, 0);

    // layer 3: h2 -> pooled (fused pooling; no h output)
    aggregate_kernel<<<warp_blocks, 256>>>(h2, off, srcs, agg);
    cudaMemsetAsync(pooled, 0, NUM_GRAPHS * HIDDEN * sizeof(float));
    sage_wmma_kernel<<<gemm_blocks, 256, SM_TOTAL>>>(agg, h2, whi + 2 * WSTRIDE, wlo + 2 * WSTRIDE, b3,
                                                     h1, batch, pooled, 0, 1);

    // head
    out_kernel<<<(NUM_GRAPHS * N_CLASSES + 127) / 128, 128>>>(pooled, Wout, bout, out);
}

// round 16
// speedup vs baseline: 1.1074x; 1.1074x over previous
#include <cuda_runtime.h>
#include <cuda_bf16.h>
#include <mma.h>
#include <cstdint>

using namespace nvcuda;

#define N_NODES   100000
#define N_EDGES   1600000
#define D_FEAT    128
#define HIDDEN    128
#define N_CLASSES 10
#define NUM_GRAPHS 64
#define N_PAD     100096   // 782 * 128, full-tile padding for direct wmma stores
#define NBLK      391      // ceil(N_NODES / 256)

typedef __nv_bfloat16 bf16;
typedef __nv_bfloat162 bf162;

#define LDT 72             // padded bf16 row length for 64-col tiles

// ---------------- scratch (no allocs allowed) ----------------
__device__ float g_agg[(size_t)N_PAD * 128];
__device__ float g_h1 [(size_t)N_PAD * 128];
__device__ float g_h2 [(size_t)N_PAD * 128];
// weights pre-split, chunk-tiled SMEM-ready: [3 layers][4 chunks][128 n][LDT]
__device__ bf16  g_whi[3 * 4 * 128 * LDT];
__device__ bf16  g_wlo[3 * 4 * 128 * LDT];
__device__ float g_pooled[NUM_GRAPHS * HIDDEN];
__device__ int   g_deg [N_NODES];
__device__ int   g_off [N_NODES + 1];
__device__ int   g_cur [N_NODES];
__device__ int   g_srcs[N_EDGES];
__device__ int   g_blksum[NBLK];
__device__ int   g_blkoff[NBLK];

// ---------------- helpers ----------------
__device__ __forceinline__ uint32_t smem_u32(const void* p) {
    uint32_t a;
    asm("{ .reg .u64 t; cvta.to.shared.u64 t, %1; cvt.u32.u64 %0, t; }" : "=r"(a) : "l"(p));
    return a;
}
__device__ __forceinline__ void cp16(uint32_t dst, const void* src) {
    asm volatile("cp.async.cg.shared.global [%0], [%1], 16;" :: "r"(dst), "l"(src));
}
#define CP_COMMIT() asm volatile("cp.async.commit_group;" ::: "memory")
#define CP_WAIT1()  asm volatile("cp.async.wait_group 1;" ::: "memory")
#define CP_WAIT0()  asm volatile("cp.async.wait_group 0;" ::: "memory")

__device__ __forceinline__ void split4(float4 v, uint2& hi, uint2& lo) {
    bf162 h0, h1, l0, l1;
    h0.x = __float2bfloat16(v.x); h0.y = __float2bfloat16(v.y);
    h1.x = __float2bfloat16(v.z); h1.y = __float2bfloat16(v.w);
    l0.x = __float2bfloat16(v.x - __bfloat162float(h0.x));
    l0.y = __float2bfloat16(v.y - __bfloat162float(h0.y));
    l1.x = __float2bfloat16(v.z - __bfloat162float(h1.x));
    l1.y = __float2bfloat16(v.w - __bfloat162float(h1.y));
    hi.x = *reinterpret_cast<uint32_t*>(&h0); hi.y = *reinterpret_cast<uint32_t*>(&h1);
    lo.x = *reinterpret_cast<uint32_t*>(&l0); lo.y = *reinterpret_cast<uint32_t*>(&l1);
}

// ---------------- weight conversion (one-time) ----------------
__global__ void __launch_bounds__(256) cvt_w_kernel(
    const float* __restrict__ W1l, const float* __restrict__ W1r,
    const float* __restrict__ W2l, const float* __restrict__ W2r,
    const float* __restrict__ W3l, const float* __restrict__ W3r,
    bf16* __restrict__ whi, bf16* __restrict__ wlo)
{
    int id = blockIdx.x * blockDim.x + threadIdx.x;   // 3*128*64 quads
    if (id >= 3 * 128 * 64) return;
    int l = id / (128 * 64);
    int n = (id / 64) % 128;
    int k = (id & 63) * 4;            // 0..252
    const float* Wl = (l == 0) ? W1l : (l == 1) ? W2l : W3l;
    const float* Wr = (l == 0) ? W1r : (l == 1) ? W2r : W3r;
    float4 v;
    if (k < 128) v = __ldg(reinterpret_cast<const float4*>(Wl + n * 128 + k));
    else         v = __ldg(reinterpret_cast<const float4*>(Wr + n * 128 + k - 128));
    uint2 hi, lo;
    split4(v, hi, lo);
    int c  = k >> 6;
    int kk = k & 63;
    size_t dst = ((size_t)(l * 4 + c) * 128 + n) * LDT + kk;
    *reinterpret_cast<uint2*>(whi + dst) = hi;
    *reinterpret_cast<uint2*>(wlo + dst) = lo;
}

// ---------------- CSR build ----------------
__global__ void __launch_bounds__(256) hist_kernel(
    const int* __restrict__ ei, int* __restrict__ deg)
{
    int e = blockIdx.x * blockDim.x + threadIdx.x;
    if (e >= N_EDGES) return;
    atomicAdd(deg + __ldg(ei + N_EDGES + e), 1);
}
__global__ void __launch_bounds__(256) partial_kernel(
    const int* __restrict__ deg, int* __restrict__ blksum)
{
    __shared__ int wsum[8];
    int i = blockIdx.x * 256 + threadIdx.x;
    int v = (i < N_NODES) ? deg[i] : 0;
#pragma unroll
    for (int d = 16; d > 0; d >>= 1) v += __shfl_down_sync(0xffffffffu, v, d);
    if ((threadIdx.x & 31) == 0) wsum[threadIdx.x >> 5] = v;
    __syncthreads();
    if (threadIdx.x < 8) {
        int s = wsum[threadIdx.x];
#pragma unroll
        for (int d = 4; d > 0; d >>= 1) s += __shfl_down_sync(0xffu, s, d);
        if (threadIdx.x == 0) blksum[blockIdx.x] = s;
    }
}
__global__ void __launch_bounds__(512) scan_blocks_kernel(
    const int* __restrict__ blksum, int* __restrict__ blkoff)
{
    __shared__ int sh[512];
    int t = threadIdx.x;
    sh[t] = (t < NBLK) ? blksum[t] : 0;
    __syncthreads();
#pragma unroll
    for (int d = 1; d < 512; d <<= 1) {
        int v = (t >= d) ? sh[t - d] : 0;
        __syncthreads();
        sh[t] += v;
        __syncthreads();
    }
    if (t < NBLK) blkoff[t] = sh[t] - blksum[t];   // exclusive
}
__global__ void __launch_bounds__(256) fill_off_kernel(
    const int* __restrict__ deg, const int* __restrict__ blkoff,
    int* __restrict__ off, int* __restrict__ cur)
{
    __shared__ int sh[256];
    int t = threadIdx.x;
    int i = blockIdx.x * 256 + t;
    int v = (i < N_NODES) ? deg[i] : 0;
    sh[t] = v;
    __syncthreads();
#pragma unroll
    for (int d = 1; d < 256; d <<= 1) {
        int u = (t >= d) ? sh[t - d] : 0;
        __syncthreads();
        sh[t] += u;
        __syncthreads();
    }
    if (i < N_NODES) {
        int excl = blkoff[blockIdx.x] + sh[t] - v;
        off[i] = excl;
        cur[i] = excl;
    }
    if (blockIdx.x == 0 && t == 0) off[N_NODES] = N_EDGES;
}
__global__ void __launch_bounds__(256) fill_kernel(
    const int* __restrict__ ei, int* __restrict__ cur, int* __restrict__ srcs)
{
    int e = blockIdx.x * blockDim.x + threadIdx.x;
    if (e >= N_EDGES) return;
    int src = __ldg(ei + e);
    int dst = __ldg(ei + N_EDGES + e);
    int pos = atomicAdd(cur + dst, 1);
    srcs[pos] = src;
}

// ---------------- gather aggregation (fp32) ----------------
__global__ void __launch_bounds__(256) aggregate_kernel(
    const float* __restrict__ h,
    const int*   __restrict__ off,
    const int*   __restrict__ srcs,
    float*       __restrict__ agg)
{
    int node = (blockIdx.x * blockDim.x + threadIdx.x) >> 5;
    int lane = threadIdx.x & 31;
    if (node >= N_NODES) return;
    int b = __ldg(off + node);
    int e = __ldg(off + node + 1);
    float4 acc = make_float4(0.f, 0.f, 0.f, 0.f);
    int i = b;
    for (; i + 3 < e; i += 4) {
        int s0 = __ldg(srcs + i + 0);
        int s1 = __ldg(srcs + i + 1);
        int s2 = __ldg(srcs + i + 2);
        int s3 = __ldg(srcs + i + 3);
        float4 v0 = __ldg(reinterpret_cast<const float4*>(h + (size_t)s0 * 128) + lane);
        float4 v1 = __ldg(reinterpret_cast<const float4*>(h + (size_t)s1 * 128) + lane);
        float4 v2 = __ldg(reinterpret_cast<const float4*>(h + (size_t)s2 * 128) + lane);
        float4 v3 = __ldg(reinterpret_cast<const float4*>(h + (size_t)s3 * 128) + lane);
        acc.x += (v0.x + v1.x) + (v2.x + v3.x);
        acc.y += (v0.y + v1.y) + (v2.y + v3.y);
        acc.z += (v0.z + v1.z) + (v2.z + v3.z);
        acc.w += (v0.w + v1.w) + (v2.w + v3.w);
    }
    for (; i < e; ++i) {
        int s = __ldg(srcs + i);
        float4 v = __ldg(reinterpret_cast<const float4*>(h + (size_t)s * 128) + lane);
        acc.x += v.x; acc.y += v.y; acc.z += v.z; acc.w += v.w;
    }
    *(reinterpret_cast<float4*>(agg + (size_t)node * 128) + lane) = acc;
}

// ================ WMMA bf16x2 SAGE GEMM (R11, STS.128 A-stores) ================
#define A_HI_OFF 0
#define A_LO_OFF 18432
#define B_BASE   36864
#define B_STAGE  36864              // hi 18432 + lo 18432
#define SM_TOTAL (B_BASE + 2 * B_STAGE)   // 110592 -> 2 CTAs/SM

__device__ __forceinline__ void load_B(
    int c, uint32_t stg, const bf16* whi, const bf16* wlo, int tid)
{
    const int r = tid >> 1;          // 0..127 (n)
    const int half = (tid & 1) * 32; // k offset within chunk
    const bf16* srcH = whi + ((size_t)c * 128 + r) * LDT + half;
    const bf16* srcL = wlo + ((size_t)c * 128 + r) * LDT + half;
    uint32_t dH = stg + r * (LDT * 2) + half * 2;
    uint32_t dL = stg + 18432 + r * (LDT * 2) + half * 2;
#pragma unroll
    for (int i = 0; i < 4; ++i) {
        cp16(dH + i * 16, srcH + i * 8);
        cp16(dL + i * 16, srcL + i * 8);
    }
}

__global__ void __launch_bounds__(256)
sage_wmma_kernel(
    const float* __restrict__ agg,
    const float* __restrict__ h,
    const bf16*  __restrict__ whi,   // layer base, chunk-tiled
    const bf16*  __restrict__ wlo,
    const float* __restrict__ bias,
    float*       __restrict__ out,   // padded to N_PAD rows
    int do_relu)
{
    extern __shared__ char smem[];
    const uint32_t sbase = smem_u32(smem);
    bf16* sAhi = reinterpret_cast<bf16*>(smem + A_HI_OFF);
    bf16* sAlo = reinterpret_cast<bf16*>(smem + A_LO_OFF);

    const int tid = threadIdx.x;
    const int wid = tid >> 5;
    const int block_row = blockIdx.x * 128;

    const int row  = tid >> 1;
    const int c0   = (tid & 1) * 32;
    const bool aok = (block_row + row) < N_NODES;

    const int wm = (wid & 1) * 64;
    const int wn = (wid >> 1) * 32;

    wmma::fragment<wmma::accumulator, 16, 16, 16, float> acc[4][2];
#pragma unroll
    for (int i = 0; i < 4; ++i)
#pragma unroll
        for (int j = 0; j < 2; ++j) wmma::fill_fragment(acc[i][j], 0.f);

    load_B(0, sbase + B_BASE,           whi, wlo, tid);
    CP_COMMIT();
    load_B(1, sbase + B_BASE + B_STAGE, whi, wlo, tid);
    CP_COMMIT();

    float4 av[8];
    {
        const float* ap = agg + (size_t)(block_row + row) * 128 + c0;
#pragma unroll
        for (int j = 0; j < 8; ++j)
            av[j] = aok ? __ldg(reinterpret_cast<const float4*>(ap) + j)
                        : make_float4(0.f, 0.f, 0.f, 0.f);
    }

#pragma unroll 1
    for (int c = 0; c < 4; ++c) {
        // convert prefetched A -> bf16 hi/lo, paired STS.128
#pragma unroll
        for (int j = 0; j < 8; j += 2) {
            int eoff = row * LDT + c0 + j * 4;    // 16B-aligned byte addr
            uint2 hi0, lo0, hi1, lo1;
            split4(av[j],     hi0, lo0);
            split4(av[j + 1], hi1, lo1);
            *reinterpret_cast<uint4*>(sAhi + eoff) = make_uint4(hi0.x, hi0.y, hi1.x, hi1.y);
            *reinterpret_cast<uint4*>(sAlo + eoff) = make_uint4(lo0.x, lo0.y, lo1.x, lo1.y);
        }
        if (c < 3) CP_WAIT1(); else CP_WAIT0();
        __syncthreads();

        if (c < 3) {
            const int nc = c + 1;
            const float* Asrc = (nc < 2) ? agg : h;
            const int k0 = (nc & 1) * 64;
            const float* ap = Asrc + (size_t)(block_row + row) * 128 + k0 + c0;
#pragma unroll
            for (int j = 0; j < 8; ++j)
                av[j] = aok ? __ldg(reinterpret_cast<const float4*>(ap) + j)
                            : make_float4(0.f, 0.f, 0.f, 0.f);
        }

        const char* st = smem + B_BASE + (c & 1) * B_STAGE;
        const bf16* sBhi = reinterpret_cast<const bf16*>(st);
        const bf16* sBlo = reinterpret_cast<const bf16*>(st + 18432);

#pragma unroll
        for (int ks = 0; ks < 4; ++ks) {
            wmma::fragment<wmma::matrix_a, 16, 16, 16, bf16, wmma::row_major> fah[4], fal[4];
#pragma unroll
            for (int i = 0; i < 4; ++i) {
                wmma::load_matrix_sync(fah[i], sAhi + (wm + i * 16) * LDT + ks * 16, LDT);
                wmma::load_matrix_sync(fal[i], sAlo + (wm + i * 16) * LDT + ks * 16, LDT);
            }
#pragma unroll
            for (int j = 0; j < 2; ++j) {
                wmma::fragment<wmma::matrix_b, 16, 16, 16, bf16, wmma::col_major> fbh, fbl;
                wmma::load_matrix_sync(fbh, sBhi + (wn + j * 16) * LDT + ks * 16, LDT);
                wmma::load_matrix_sync(fbl, sBlo + (wn + j * 16) * LDT + ks * 16, LDT);
#pragma unroll
                for (int i = 0; i < 4; ++i) {
                    wmma::mma_sync(acc[i][j], fah[i], fbh, acc[i][j]);
                    wmma::mma_sync(acc[i][j], fah[i], fbl, acc[i][j]);
                    wmma::mma_sync(acc[i][j], fal[i], fbh, acc[i][j]);
                }
            }
        }
        __syncthreads();
        if (c + 2 < 4) {
            load_B(c + 2, sbase + B_BASE + (c & 1) * B_STAGE, whi, wlo, tid);
            CP_COMMIT();
        }
    }

    // ---- epilogue: replicated bias, in-fragment add/relu, direct store ----
    float* sBias = reinterpret_cast<float*>(smem);
    for (int idx = tid; idx < 16 * 128; idx += 256)
        sBias[idx] = __ldg(bias + (idx & 127));
    __syncthreads();

#pragma unroll
    for (int j = 0; j < 2; ++j) {
        wmma::fragment<wmma::accumulator, 16, 16, 16, float> bf;
        wmma::load_matrix_sync(bf, sBias + wn + j * 16, 128, wmma::mem_row_major);
#pragma unroll
        for (int i = 0; i < 4; ++i) {
#pragma unroll
            for (int e = 0; e < acc[i][j].num_elements; ++e) {
                float v = acc[i][j].x[e] + bf.x[e];
                acc[i][j].x[e] = do_relu ? fmaxf(v, 0.f) : v;
            }
            float* op = out + (size_t)(block_row + wm + i * 16) * 128 + wn + j * 16;
            wmma::store_matrix_sync(op, acc[i][j], 128, wmma::mem_row_major);
        }
    }
}

// ---------------- pooling ----------------
__global__ void __launch_bounds__(256) pool_kernel(
    const float* __restrict__ h,
    const int*   __restrict__ batch,
    float*       __restrict__ pooled)
{
    int node = (blockIdx.x * blockDim.x + threadIdx.x) >> 5;
    int lane = threadIdx.x & 31;
    if (node >= N_NODES) return;
    int g = __ldg(batch + node);
    float4 v = __ldg(reinterpret_cast<const float4*>(h + (size_t)node * 128) + lane);
    float* ap = pooled + (size_t)g * HIDDEN + lane * 4;
    asm volatile("red.global.add.v4.f32 [%0], {%1,%2,%3,%4};"
                 :: "l"(ap), "f"(v.x), "f"(v.y), "f"(v.z), "f"(v.w) : "memory");
}

// ---------------- output head ----------------
__global__ void out_kernel(
    const float* __restrict__ pooled,
    const float* __restrict__ Wout,
    const float* __restrict__ bout,
    float*       __restrict__ out)
{
    int idx = blockIdx.x * blockDim.x + threadIdx.x;
    if (idx >= NUM_GRAPHS * N_CLASSES) return;
    int g = idx / N_CLASSES;
    int c = idx % N_CLASSES;
    float s = __ldg(bout + c);
    const float* p = pooled + (size_t)g * HIDDEN;
    const float* w = Wout + (size_t)c * HIDDEN;
#pragma unroll 8
    for (int k = 0; k < HIDDEN; ++k) s = fmaf(p[k], w[k], s);
    out[idx] = s;
}

// ---------------- launch ----------------
extern "C" void kernel_launch(void* const* d_in, const int* in_sizes, int n_in,
                              void* d_out, int out_size)
{
    const float* x     = (const float*)d_in[0];
    const int*   ei    = (const int*)  d_in[1];
    const int*   batch = (const int*)  d_in[2];
    const float* W1l = (const float*)d_in[3];
    const float* b1  = (const float*)d_in[4];
    const float* W1r = (const float*)d_in[5];
    const float* W2l = (const float*)d_in[6];
    const float* b2  = (const float*)d_in[7];
    const float* W2r = (const float*)d_in[8];
    const float* W3l = (const float*)d_in[9];
    const float* b3  = (const float*)d_in[10];
    const float* W3r = (const float*)d_in[11];
    const float* Wout = (const float*)d_in[12];
    const float* bout = (const float*)d_in[13];
    float* out = (float*)d_out;

    float *agg, *h1, *h2, *pooled;
    bf16 *whi, *wlo;
    int *deg, *off, *cur, *srcs, *blksum, *blkoff;
    cudaGetSymbolAddress((void**)&agg,    g_agg);
    cudaGetSymbolAddress((void**)&h1,     g_h1);
    cudaGetSymbolAddress((void**)&h2,     g_h2);
    cudaGetSymbolAddress((void**)&whi,    g_whi);
    cudaGetSymbolAddress((void**)&wlo,    g_wlo);
    cudaGetSymbolAddress((void**)&pooled, g_pooled);
    cudaGetSymbolAddress((void**)&deg,    g_deg);
    cudaGetSymbolAddress((void**)&off,    g_off);
    cudaGetSymbolAddress((void**)&cur,    g_cur);
    cudaGetSymbolAddress((void**)&srcs,   g_srcs);
    cudaGetSymbolAddress((void**)&blksum, g_blksum);
    cudaGetSymbolAddress((void**)&blkoff, g_blkoff);

    cudaFuncSetAttribute(sage_wmma_kernel,
                         cudaFuncAttributeMaxDynamicSharedMemorySize, SM_TOTAL);

    const int edge_blocks = (N_EDGES + 255) / 256;
    const int node_blocks = NBLK;
    const int gemm_blocks = N_PAD / 128;   // 782
    const int warp_blocks = (N_NODES * 32 + 255) / 256;
    const int WSTRIDE = 4 * 128 * LDT;     // per-layer weight stride

    // one-time weight conversion
    cvt_w_kernel<<<(3 * 128 * 64 + 255) / 256, 256>>>(W1l, W1r, W2l, W2r, W3l, W3r, whi, wlo);

    // CSR build (multi-block scan)
    cudaMemsetAsync(deg, 0, N_NODES * sizeof(int));
    hist_kernel<<<edge_blocks, 256>>>(ei, deg);
    partial_kernel<<<node_blocks, 256>>>(deg, blksum);
    scan_blocks_kernel<<<1, 512>>>(blksum, blkoff);
    fill_off_kernel<<<node_blocks, 256>>>(deg, blkoff, off, cur);
    fill_kernel<<<edge_blocks, 256>>>(ei, cur, srcs);

    // layer 1: x -> h1
    aggregate_kernel<<<warp_blocks, 256>>>(x, off, srcs, agg);
    sage_wmma_kernel<<<gemm_blocks, 256, SM_TOTAL>>>(agg, x, whi, wlo, b1, h1, 1);

    // layer 2: h1 -> h2
    aggregate_kernel<<<warp_blocks, 256>>>(h1, off, srcs, agg);
    sage_wmma_kernel<<<gemm_blocks, 256, SM_TOTAL>>>(agg, h1, whi + WSTRIDE, wlo + WSTRIDE, b2, h2, 1);

    // layer 3: h2 -> h1 (no relu)
    aggregate_kernel<<<warp_blocks, 256>>>(h2, off, srcs, agg);
    sage_wmma_kernel<<<gemm_blocks, 256, SM_TOTAL>>>(agg, h2, whi + 2 * WSTRIDE, wlo + 2 * WSTRIDE, b3, h1, 0);

    // pool + head
    cudaMemsetAsync(pooled, 0, NUM_GRAPHS * HIDDEN * sizeof(float));
    pool_kernel<<<warp_blocks, 256>>>(h1, batch, pooled);
    out_kernel<<<(NUM_GRAPHS * N_CLASSES + 127) / 128, 128>>>(pooled, Wout, bout, out);
}